// round 14
// baseline (speedup 1.0000x reference)
#include <cuda_runtime.h>
#include <cuda_fp16.h>
#include <math.h>
#include <stdint.h>

// ---------------- problem constants ----------------
#define BB 64
#define TT 243
#define JJ 17
#define DD 256
#define DH 128
#define TR 60
#define KSEL 30
#define KSJ (KSEL*JJ)          // 510
#define YROWS (BB*KSJ)         // 32640
#define MROWS (BB*TT*JJ)       // 264384
#define TJ (TT*JJ)             // 4131

// ---------------- scratch ----------------
__device__ float g_xd[(size_t)BB*TR*JJ*DD];
__device__ float g_score[BB*TR];
__device__ int   g_topidx[BB*KSEL];
__device__ float g_Y[(size_t)YROWS*DD];
__device__ float g_musel[YROWS], g_qsel[YROWS];
__device__ float g_q01[BB*(KSEL-1)*JJ];
__device__ float g_c1fp[DD], g_c2fp[DD];
__device__ float g_c1op[DD], g_c2op[DD];
__device__ __half g_w0f[DD*DD];     // (fp_g ⊙ fp_w)^T fp16
__device__ __half g_w1f[DD*DD];     // (op_g ⊙ op_w)^T fp16

__device__ __forceinline__ float gelu_f(float x) {
    return 0.5f * x * (1.0f + erff(x * 0.70710678118654752f));
}
__device__ __forceinline__ uint32_t smem_u32(const void* p) {
    uint32_t a;
    asm("{ .reg .u64 t; cvta.to.shared.u64 t, %1; cvt.u32.u64 %0, t; }" : "=r"(a) : "l"(p));
    return a;
}
__device__ __forceinline__ void mma_f16(float* d, const uint32_t* a,
                                        uint32_t b0, uint32_t b1) {
    asm volatile(
        "mma.sync.aligned.m16n8k16.row.col.f32.f16.f16.f32 "
        "{%0,%1,%2,%3}, {%4,%5,%6,%7}, {%8,%9}, {%0,%1,%2,%3};"
        : "+f"(d[0]), "+f"(d[1]), "+f"(d[2]), "+f"(d[3])
        : "r"(a[0]), "r"(a[1]), "r"(a[2]), "r"(a[3]), "r"(b0), "r"(b1));
}
#define LDSM4(r, addr) \
    asm volatile("ldmatrix.sync.aligned.m8n8.x4.shared.b16 {%0,%1,%2,%3}, [%4];" \
        : "=r"((r)[0]), "=r"((r)[1]), "=r"((r)[2]), "=r"((r)[3]) : "r"(addr))
#define CP_ASYNC(dst, src) asm volatile("cp.async.cg.shared.global [%0], [%1], 16;" :: "r"(dst), "l"(src))
#define CP_COMMIT()        asm volatile("cp.async.commit_group;" ::: "memory")
#define CP_WAIT(n)         asm volatile("cp.async.wait_group %0;" :: "n"(n) : "memory")

// smem geometry (3-stage pipeline)
#define RSTR 40
#define RAWB (64*RSTR)          // 2560 floats per raw A buffer
#define BSTR 20
#define BB_  (256*BSTR)         // 5120 u32 per B buffer (fp16)
#define HDR 832
// compute region: 3*RAWB + 3*BB_ = 23040 units; epilogue stage needs 64*258 = 16512
#define SMEM_G ((HDR + 3*RAWB + 3*BB_) * 4)   // 95488 B
#define ESTR 258

// ---------------- prep: both weights, W' = gamma ⊙ W, transpose to fp16 ----------------
__global__ __launch_bounds__(256) void prep_w2(
    const float* __restrict__ W0, const float* __restrict__ g0,
    const float* __restrict__ W1, const float* __restrict__ g1,
    __half* __restrict__ W0f, __half* __restrict__ W1f)
{
    int which = blockIdx.x >> 8;
    int idx = (blockIdx.x & 255) * 256 + threadIdx.x;
    int k = idx >> 8, n = idx & 255;
    const float* W = which ? W1 : W0;
    const float* g = which ? g1 : g0;
    float w = W[idx] * g[k];
    (which ? W1f : W0f)[n * DD + k] = __float2half_rn(w);
}

// ---------------- prep: c1[n] = beta@W + bias[n], c2[n] = gamma@W (both) ----------------
__global__ __launch_bounds__(256) void calc_c2(
    const float* __restrict__ W0, const float* __restrict__ be0,
    const float* __restrict__ ga0, const float* __restrict__ bi0,
    const float* __restrict__ W1, const float* __restrict__ be1,
    const float* __restrict__ ga1, const float* __restrict__ bi1,
    float* __restrict__ c1a, float* __restrict__ c2a,
    float* __restrict__ c1b, float* __restrict__ c2b)
{
    __shared__ float r1[256], r2[256];
    int which = blockIdx.x >> 8;
    int n = blockIdx.x & 255, k = threadIdx.x;
    const float* W = which ? W1 : W0;
    float w = W[k * DD + n];
    r1[k] = (which ? be1 : be0)[k] * w;
    r2[k] = (which ? ga1 : ga0)[k] * w;
    __syncthreads();
    #pragma unroll
    for (int s = 128; s > 0; s >>= 1) {
        if (k < s) { r1[k] += r1[k + s]; r2[k] += r2[k + s]; }
        __syncthreads();
    }
    if (k == 0) {
        (which ? c1b : c1a)[n] = r1[0] + (which ? bi1 : bi0)[n];
        (which ? c2b : c2a)[n] = r2[0];
    }
}

// ---------------- fp16 x1 mma GEMM, 3-stage cp.async pipeline ----------------
// MODE 0: A = raw x t-slab of (b,j); epilogue gelu(affine) + pool -> g_xd
// MODE 1: A = selected xd rows; plain Y store + row stats
template <int MODE>
__global__ __launch_bounds__(256, 2) void gemm_f(
    const float* __restrict__ X,
    const __half* __restrict__ Wf,
    const float* __restrict__ c1, const float* __restrict__ c2,
    float* __restrict__ out)
{
    extern __shared__ float smem[];
    float* sc1 = smem;
    float* sc2 = smem + 256;
    float* smu = smem + 512;
    float* srs = smem + 576;
    float* sAr = smem + HDR;                            // [3][64][RSTR] raw fp32
    uint32_t* sB = (uint32_t*)(smem + HDR + 3 * RAWB);  // [3][256][BSTR] fp16
    float* sepi = smem + HDR;

    const int tid  = threadIdx.x;
    const int wid  = tid >> 5;
    const int lane = tid & 31;
    const int warp_m = (wid & 1) * 32;
    const int warp_n = (wid >> 1) * 64;
    const int R  = lane >> 2;
    const int cq = lane & 3;
    const int aq = tid & 7;

    int b_ = 0, j_ = 0, ts = 0, rows = 64, r0 = 0, m0 = 0;
    if (MODE == 0) {
        int bj = blockIdx.x >> 2, tile = blockIdx.x & 3;
        b_ = bj / JJ; j_ = bj % JJ;
        r0 = tile * 15;
        ts = (r0 * TT) / TR;
        int te = ((r0 + 15) * TT + TR - 1) / TR;
        rows = te - ts;
        sc1[tid] = c1[tid];
        sc2[tid] = c2[tid];
    } else {
        m0 = blockIdx.x * 64;
    }

    int offA0[2];
    #pragma unroll
    for (int it = 0; it < 2; ++it) {
        int row = (tid >> 3) + it * 32;
        if (MODE == 0) {
            int rc = min(row, rows - 1);
            offA0[it] = ((b_ * TT + ts + rc) * JJ + j_) * DD + aq * 4;
        } else {
            int yrow = m0 + row;
            int b = yrow / KSJ;
            int rem = yrow % KSJ;
            int s = rem / JJ, j = rem % JJ;
            offA0[it] = ((b * TR + g_topidx[b * KSEL + s]) * JJ + j) * DD + aq * 4;
        }
    }
    const float* Asrc = (MODE == 0) ? X : &g_xd[0];
    const bool stats_on = (wid < 2);
    float sAc[4] = {0,0,0,0}, ssAc[4] = {0,0,0,0};

    float acc[2][8][4];
    #pragma unroll
    for (int i = 0; i < 2; i++)
        #pragma unroll
        for (int j = 0; j < 8; j++)
            #pragma unroll
            for (int q = 0; q < 4; q++) acc[i][j][q] = 0.0f;

    const uint32_t bBase = smem_u32(sB) +
        4 * ((warp_n + (lane & 7) + ((lane >> 4) & 1) * 8) * BSTR + ((lane >> 3) & 1) * 4);

    auto stageA = [&](int kt, int buf) {
        #pragma unroll
        for (int it = 0; it < 2; ++it) {
            int row = (tid >> 3) + it * 32;
            uint32_t d = smem_u32(sAr + buf * RAWB + row * RSTR + aq * 4);
            CP_ASYNC(d, Asrc + offA0[it] + kt);
        }
    };
    auto stageB = [&](int kt, int buf) {
        #pragma unroll
        for (int it = 0; it < 4; ++it) {
            int f = tid + it * 256;
            int n = f >> 2;
            int q = f & 3;
            uint32_t dh = smem_u32(sB + buf * BB_ + n * BSTR + q * 4);
            CP_ASYNC(dh, Wf + (size_t)n * DD + kt + q * 8);
        }
    };

    // ---- prologue: 2 chunks in flight ----
    stageA(0, 0); stageB(0, 0); CP_COMMIT();
    stageA(32, 1); stageB(32, 1); CP_COMMIT();

    // ---- main loop: 1 barrier/chunk, 2-chunk-deep pipeline ----
    #pragma unroll 1
    for (int c = 0; c < 8; ++c) {
        const int buf = c % 3;
        if (c < 7) CP_WAIT(1); else CP_WAIT(0);   // chunk c complete
        __syncthreads();                          // publish chunk c; free buf (c+2)%3
        if (c + 2 < 8) {
            stageA((c + 2) * 32, (c + 2) % 3);
            stageB((c + 2) * 32, (c + 2) % 3);
            CP_COMMIT();
        }

        #pragma unroll
        for (int ks = 0; ks < 2; ++ks) {
            // build A fp16 fragments from raw smem
            uint32_t ah[2][4];
            #pragma unroll
            for (int mt = 0; mt < 2; ++mt) {
                #pragma unroll
                for (int pr = 0; pr < 2; ++pr) {
                    int row = warp_m + mt * 16 + pr * 8 + R;
                    const float* bp = sAr + buf * RAWB + row * RSTR + ks * 16 + 2 * cq;
                    float2 v0 = *(const float2*)bp;
                    float2 v1 = *(const float2*)(bp + 8);
                    if (stats_on) {
                        int sl = mt * 2 + pr;
                        sAc[sl]  += v0.x + v0.y + v1.x + v1.y;
                        ssAc[sl] += v0.x*v0.x + v0.y*v0.y + v1.x*v1.x + v1.y*v1.y;
                    }
                    __half2 h0 = __floats2half2_rn(v0.x, v0.y);
                    __half2 h1 = __floats2half2_rn(v1.x, v1.y);
                    ah[mt][pr]     = *(uint32_t*)&h0;
                    ah[mt][2 + pr] = *(uint32_t*)&h1;
                }
            }
            // B fragments + MMAs
            #pragma unroll
            for (int p = 0; p < 4; ++p) {
                uint32_t bf[4];
                LDSM4(bf, bBase + 4 * (buf * BB_ + p * 16 * BSTR + ks * 8));
                const int n0 = 2 * p, n1 = 2 * p + 1;
                mma_f16(acc[0][n0], ah[0], bf[0], bf[1]);
                mma_f16(acc[1][n0], ah[1], bf[0], bf[1]);
                mma_f16(acc[0][n1], ah[0], bf[2], bf[3]);
                mma_f16(acc[1][n1], ah[1], bf[2], bf[3]);
            }
        }
    }
    __syncthreads();

    // ---- finalize row stats (warps 0,1 own rows 0-63) ----
    if (stats_on) {
        #pragma unroll
        for (int sl = 0; sl < 4; ++sl) {
            float s_ = sAc[sl], ss_ = ssAc[sl];
            #pragma unroll
            for (int o = 1; o <= 2; o <<= 1) {
                s_  += __shfl_xor_sync(0xffffffffu, s_,  o);
                ss_ += __shfl_xor_sync(0xffffffffu, ss_, o);
            }
            if (cq == 0) {
                int row = warp_m + (sl >> 1) * 16 + (sl & 1) * 8 + R;
                float mu = s_ * (1.0f / DD);
                float ms = ss_ * (1.0f / DD);
                if (MODE == 0) {
                    smu[row] = mu;
                    srs[row] = rsqrtf(ms - mu * mu + 1e-5f);
                } else {
                    g_musel[m0 + row] = mu;
                    g_qsel[m0 + row]  = ms;
                }
            }
        }
    }

    // ---- epilogue ----
    if (MODE == 0) {
        __syncthreads();
        #pragma unroll
        for (int mt = 0; mt < 2; ++mt) {
            int mrow = warp_m + mt * 16 + R;
            float muA = smu[mrow],     rsA = srs[mrow];
            float muB = smu[mrow + 8], rsB = srs[mrow + 8];
            #pragma unroll
            for (int nt = 0; nt < 8; ++nt) {
                int n = warp_n + nt * 8 + 2 * cq;
                float2 cc1 = *(float2*)(sc1 + n);
                float2 cc2 = *(float2*)(sc2 + n);
                *(float2*)(sepi + mrow * ESTR + n) = make_float2(
                    gelu_f(rsA * acc[mt][nt][0] + cc1.x - muA * rsA * cc2.x),
                    gelu_f(rsA * acc[mt][nt][1] + cc1.y - muA * rsA * cc2.y));
                *(float2*)(sepi + (mrow + 8) * ESTR + n) = make_float2(
                    gelu_f(rsB * acc[mt][nt][2] + cc1.x - muB * rsB * cc2.x),
                    gelu_f(rsB * acc[mt][nt][3] + cc1.y - muB * rsB * cc2.y));
            }
        }
        __syncthreads();
        const int col = tid;
        #pragma unroll
        for (int rl = 0; rl < 15; ++rl) {
            int rg = r0 + rl;
            int s = (rg * TT) / TR - ts;
            int e = ((rg + 1) * TT + TR - 1) / TR - ts;
            float a = 0.0f;
            for (int t = s; t < e; ++t) a += sepi[t * ESTR + col];
            out[((size_t)((b_ * TR + rg) * JJ + j_)) * DD + col] = a / (float)(e - s);
        }
    } else {
        #pragma unroll
        for (int mt = 0; mt < 2; ++mt) {
            int mrow = m0 + warp_m + mt * 16 + R;
            #pragma unroll
            for (int nt = 0; nt < 8; ++nt) {
                int n = warp_n + nt * 8 + 2 * cq;
                *(float2*)(out + (size_t)mrow * DD + n) =
                    make_float2(acc[mt][nt][0], acc[mt][nt][1]);
                *(float2*)(out + (size_t)(mrow + 8) * DD + n) =
                    make_float2(acc[mt][nt][2], acc[mt][nt][3]);
            }
        }
    }
}

// ---------------- scorer (fused J-mean): grid BB*4, 15 r's each ----------------
__global__ __launch_bounds__(128) void scorer_score(
    const float* __restrict__ w1, const float* __restrict__ b1,
    const float* __restrict__ w2, const float* __restrict__ b2)
{
    extern __shared__ float sw1[];
    __shared__ float spm[DD];
    __shared__ float red[DH];
    int b = blockIdx.x >> 2, grp = blockIdx.x & 3;
    int tid = threadIdx.x;

    #pragma unroll 8
    for (int i = tid; i < DD * DH / 4; i += 128)
        *(float4*)(sw1 + i * 4) = *(const float4*)(w1 + i * 4);
    float b1v = b1[tid];
    float w2v = w2[tid];
    float b2v = b2[0];
    __syncthreads();

    for (int rl = 0; rl < 15; ++rl) {
        int r = grp * 15 + rl;
        // fused pooled-mean over J
        float m0 = 0.0f, m1 = 0.0f;
        const float* base = g_xd + (size_t)((b * TR + r) * JJ) * DD;
        #pragma unroll
        for (int j = 0; j < JJ; ++j) {
            m0 += base[j * DD + tid];
            m1 += base[j * DD + tid + 128];
        }
        spm[tid]       = m0 * (1.0f / JJ);
        spm[tid + 128] = m1 * (1.0f / JJ);
        __syncthreads();
        float acc = b1v;
        #pragma unroll 8
        for (int c = 0; c < DD; ++c)
            acc = fmaf(spm[c], sw1[c * DH + tid], acc);
        red[tid] = gelu_f(acc) * w2v;
        __syncthreads();
        #pragma unroll
        for (int s = 64; s > 0; s >>= 1) {
            if (tid < s) red[tid] += red[tid + s];
            __syncthreads();
        }
        if (tid == 0)
            g_score[b * TR + r] = 1.0f / (1.0f + expf(-(red[0] + b2v)));
        __syncthreads();
    }
}

// ---------------- top-k selection ----------------
__global__ __launch_bounds__(64) void topk_kernel() {
    __shared__ float sc[TR];
    __shared__ int sel[TR];
    int b = blockIdx.x, tid = threadIdx.x;
    if (tid < TR) sc[tid] = g_score[b * TR + tid];
    __syncthreads();
    if (tid < TR) {
        float s = sc[tid];
        int rank = 0;
        for (int q = 0; q < TR; ++q) {
            float sq = sc[q];
            rank += (sq > s) || (sq == s && q < tid);
        }
        sel[tid] = (rank < KSEL) ? 1 : 0;
    }
    __syncthreads();
    if (tid == 0) {
        int pos = 0;
        for (int r = 0; r < TR; ++r)
            if (sel[r]) g_topidx[b * KSEL + (pos++)] = r;
    }
}

// ---------------- cross-dot: E[xd_sel[p] * xd_sel[p+1]] ----------------
__global__ __launch_bounds__(256) void crossdot_kernel() {
    int id = blockIdx.x * 8 + (threadIdx.x >> 5);
    int lane = threadIdx.x & 31;
    if (id >= BB * (KSEL - 1) * JJ) return;
    int j = id % JJ;
    int p = (id / JJ) % (KSEL - 1);
    int b = id / (JJ * (KSEL - 1));
    int i0 = g_topidx[b * KSEL + p];
    int i1 = g_topidx[b * KSEL + p + 1];
    const float* r0 = g_xd + (size_t)((b * TR + i0) * JJ + j) * DD;
    const float* r1 = g_xd + (size_t)((b * TR + i1) * JJ + j) * DD;
    float s = 0.0f;
    #pragma unroll
    for (int h = 0; h < 2; ++h) {
        int c = h * 128 + lane * 4;
        float4 a = *(const float4*)(r0 + c);
        float4 d = *(const float4*)(r1 + c);
        s += a.x*d.x + a.y*d.y + a.z*d.z + a.w*d.w;
    }
    #pragma unroll
    for (int o = 16; o > 0; o >>= 1)
        s += __shfl_xor_sync(0xffffffffu, s, o);
    if (lane == 0) g_q01[id] = s * (1.0f / DD);
}

// ---------------- final epilogue: lerp(Y) affine + gelu + residual ----------------
__global__ __launch_bounds__(256) void epilogue_e(const float* __restrict__ X,
                                                  float* __restrict__ out) {
    int m = blockIdx.x * 8 + (threadIdx.x >> 5);
    int lane = threadIdx.x & 31;
    int b = m / TJ, rem = m % TJ;
    int t = rem / JJ, j = rem % JJ;

    float src = (t + 0.5f) * (float)(30.0 / 243.0) - 0.5f;
    src = fminf(fmaxf(src, 0.0f), (float)(KSEL - 1));
    int x0 = (int)src;
    int x1 = min(x0 + 1, KSEL - 1);
    float w = src - (float)x0;

    int ys0 = (b * KSEL + x0) * JJ + j;
    int ys1 = (b * KSEL + x1) * JJ + j;
    float mu0 = g_musel[ys0], q0 = g_qsel[ys0];
    float mu1 = g_musel[ys1], q1 = g_qsel[ys1];
    float q01 = (x1 > x0) ? g_q01[(b * (KSEL - 1) + x0) * JJ + j] : q0;
    float iw = 1.0f - w;
    float mu = iw * mu0 + w * mu1;
    float es = iw * iw * q0 + 2.0f * w * iw * q01 + w * w * q1;
    float rs = rsqrtf(es - mu * mu + 1e-5f);
    float mrs = mu * rs;

    const float* y0 = g_Y + (size_t)ys0 * DD;
    const float* y1 = g_Y + (size_t)ys1 * DD;
    #pragma unroll
    for (int h = 0; h < 2; ++h) {
        int c = h * 128 + lane * 4;
        float4 a = *(const float4*)(y0 + c);
        float4 d = *(const float4*)(y1 + c);
        float4 cc1 = *(const float4*)(g_c1op + c);
        float4 cc2 = *(const float4*)(g_c2op + c);
        float4 xr = *(const float4*)(X + (size_t)m * DD + c);
        float4 o;
        o.x = gelu_f(rs * (a.x + (d.x - a.x) * w) + cc1.x - mrs * cc2.x) + xr.x;
        o.y = gelu_f(rs * (a.y + (d.y - a.y) * w) + cc1.y - mrs * cc2.y) + xr.y;
        o.z = gelu_f(rs * (a.z + (d.z - a.z) * w) + cc1.z - mrs * cc2.z) + xr.z;
        o.w = gelu_f(rs * (a.w + (d.w - a.w) * w) + cc1.w - mrs * cc2.w) + xr.w;
        *(float4*)(out + (size_t)m * DD + c) = o;
    }
}

// ---------------- launch ----------------
#define SMEM_SC (DD * DH * 4)

extern "C" void kernel_launch(void* const* d_in, const int* in_sizes, int n_in,
                              void* d_out, int out_size) {
    const float* x       = (const float*)d_in[0];
    const float* fp_g    = (const float*)d_in[1];
    const float* fp_b    = (const float*)d_in[2];
    const float* fp_w    = (const float*)d_in[3];
    const float* fp_bias = (const float*)d_in[4];
    const float* sc_w1   = (const float*)d_in[5];
    const float* sc_b1   = (const float*)d_in[6];
    const float* sc_w2   = (const float*)d_in[7];
    const float* sc_b2   = (const float*)d_in[8];
    const float* op_g    = (const float*)d_in[9];
    const float* op_b    = (const float*)d_in[10];
    const float* op_w    = (const float*)d_in[11];
    const float* op_bias = (const float*)d_in[12];
    float* out = (float*)d_out;

    float *xd_ptr, *y_ptr, *c1fp, *c2fp, *c1op, *c2op;
    __half *w0f, *w1f;
    cudaGetSymbolAddress((void**)&xd_ptr, g_xd);
    cudaGetSymbolAddress((void**)&y_ptr, g_Y);
    cudaGetSymbolAddress((void**)&c1fp, g_c1fp);
    cudaGetSymbolAddress((void**)&c2fp, g_c2fp);
    cudaGetSymbolAddress((void**)&c1op, g_c1op);
    cudaGetSymbolAddress((void**)&c2op, g_c2op);
    cudaGetSymbolAddress((void**)&w0f, g_w0f);
    cudaGetSymbolAddress((void**)&w1f, g_w1f);

    cudaFuncSetAttribute(gemm_f<0>, cudaFuncAttributeMaxDynamicSharedMemorySize, SMEM_G);
    cudaFuncSetAttribute(gemm_f<1>, cudaFuncAttributeMaxDynamicSharedMemorySize, SMEM_G);
    cudaFuncSetAttribute(scorer_score, cudaFuncAttributeMaxDynamicSharedMemorySize, SMEM_SC);

    prep_w2<<<512, 256>>>(fp_w, fp_g, op_w, op_g, w0f, w1f);
    calc_c2<<<512, 256>>>(fp_w, fp_b, fp_g, fp_bias, op_w, op_b, op_g, op_bias,
                          c1fp, c2fp, c1op, c2op);
    gemm_f<0><<<BB * JJ * 4, 256, SMEM_G>>>(x, w0f, c1fp, c2fp, xd_ptr);
    scorer_score<<<BB * 4, 128, SMEM_SC>>>(sc_w1, sc_b1, sc_w2, sc_b2);
    topk_kernel<<<BB, 64>>>();
    gemm_f<1><<<YROWS / 64, 256, SMEM_G>>>(x, w1f, c1op, c2op, y_ptr);
    crossdot_kernel<<<(BB * (KSEL - 1) * JJ + 7) / 8, 256>>>();
    epilogue_e<<<MROWS / 8, 256>>>(x, out);
}

// round 15
// speedup vs baseline: 1.1554x; 1.1554x over previous
#include <cuda_runtime.h>
#include <cuda_fp16.h>
#include <math.h>
#include <stdint.h>

// ---------------- problem constants ----------------
#define BB 64
#define TT 243
#define JJ 17
#define DD 256
#define DH 128
#define TR 60
#define KSEL 30
#define KSJ (KSEL*JJ)          // 510
#define YROWS (BB*KSJ)         // 32640
#define MROWS (BB*TT*JJ)       // 264384
#define TJ (TT*JJ)             // 4131

// ---------------- scratch ----------------
__device__ float g_xd[(size_t)BB*TR*JJ*DD];
__device__ float g_pm[(size_t)BB*TR*DD];
__device__ float g_score[BB*TR];
__device__ int   g_topidx[BB*KSEL];
__device__ float g_Y[(size_t)YROWS*DD];
__device__ float g_musel[YROWS], g_qsel[YROWS];
__device__ float g_q01[BB*(KSEL-1)*JJ];
__device__ float g_c1fp[DD], g_c2fp[DD];
__device__ float g_c1op[DD], g_c2op[DD];
__device__ __half g_w0f[DD*DD];     // (fp_g ⊙ fp_w)^T fp16
__device__ __half g_w1f[DD*DD];     // (op_g ⊙ op_w)^T fp16

__device__ __forceinline__ float gelu_f(float x) {
    return 0.5f * x * (1.0f + erff(x * 0.70710678118654752f));
}
__device__ __forceinline__ uint32_t smem_u32(const void* p) {
    uint32_t a;
    asm("{ .reg .u64 t; cvta.to.shared.u64 t, %1; cvt.u32.u64 %0, t; }" : "=r"(a) : "l"(p));
    return a;
}
__device__ __forceinline__ void mma_f16(float* d, const uint32_t* a,
                                        uint32_t b0, uint32_t b1) {
    asm volatile(
        "mma.sync.aligned.m16n8k16.row.col.f32.f16.f16.f32 "
        "{%0,%1,%2,%3}, {%4,%5,%6,%7}, {%8,%9}, {%0,%1,%2,%3};"
        : "+f"(d[0]), "+f"(d[1]), "+f"(d[2]), "+f"(d[3])
        : "r"(a[0]), "r"(a[1]), "r"(a[2]), "r"(a[3]), "r"(b0), "r"(b1));
}
#define LDSM4(r, addr) \
    asm volatile("ldmatrix.sync.aligned.m8n8.x4.shared.b16 {%0,%1,%2,%3}, [%4];" \
        : "=r"((r)[0]), "=r"((r)[1]), "=r"((r)[2]), "=r"((r)[3]) : "r"(addr))
#define CP_ASYNC(dst, src) asm volatile("cp.async.cg.shared.global [%0], [%1], 16;" :: "r"(dst), "l"(src))
#define CP_COMMIT()        asm volatile("cp.async.commit_group;" ::: "memory")
#define CP_WAIT(n)         asm volatile("cp.async.wait_group %0;" :: "n"(n) : "memory")

// smem geometry (round-13 2-stage pipeline)
#define RSTR 40
#define RAWB (64*RSTR)          // 2560 floats per raw A buffer
#define BSTR 20
#define BB_  (256*BSTR)         // 5120 u32 per B buffer (fp16)
#define HDR 832
#define SMEM_G ((HDR + 16512) * 4)   // 69376 B
#define ESTR 258

// ---------------- prep: both weights, W' = gamma ⊙ W, transpose to fp16 ----------------
__global__ __launch_bounds__(256) void prep_w2(
    const float* __restrict__ W0, const float* __restrict__ g0,
    const float* __restrict__ W1, const float* __restrict__ g1,
    __half* __restrict__ W0f, __half* __restrict__ W1f)
{
    int which = blockIdx.x >> 8;
    int idx = (blockIdx.x & 255) * 256 + threadIdx.x;
    int k = idx >> 8, n = idx & 255;
    const float* W = which ? W1 : W0;
    const float* g = which ? g1 : g0;
    float w = W[idx] * g[k];
    (which ? W1f : W0f)[n * DD + k] = __float2half_rn(w);
}

// ---------------- prep: c1[n] = beta@W + bias[n], c2[n] = gamma@W (both) ----------------
__global__ __launch_bounds__(256) void calc_c2(
    const float* __restrict__ W0, const float* __restrict__ be0,
    const float* __restrict__ ga0, const float* __restrict__ bi0,
    const float* __restrict__ W1, const float* __restrict__ be1,
    const float* __restrict__ ga1, const float* __restrict__ bi1,
    float* __restrict__ c1a, float* __restrict__ c2a,
    float* __restrict__ c1b, float* __restrict__ c2b)
{
    __shared__ float r1[256], r2[256];
    int which = blockIdx.x >> 8;
    int n = blockIdx.x & 255, k = threadIdx.x;
    const float* W = which ? W1 : W0;
    float w = W[k * DD + n];
    r1[k] = (which ? be1 : be0)[k] * w;
    r2[k] = (which ? ga1 : ga0)[k] * w;
    __syncthreads();
    #pragma unroll
    for (int s = 128; s > 0; s >>= 1) {
        if (k < s) { r1[k] += r1[k + s]; r2[k] += r2[k + s]; }
        __syncthreads();
    }
    if (k == 0) {
        (which ? c1b : c1a)[n] = r1[0] + (which ? bi1 : bi0)[n];
        (which ? c2b : c2a)[n] = r2[0];
    }
}

// ---------------- fp16 x1 mma GEMM (round-13 2-stage pipeline) ----------------
// MODE 0: A = raw x t-slab of (b,j); epilogue gelu(affine) + pool -> g_xd
// MODE 1: A = selected xd rows; plain Y store + row stats
template <int MODE>
__global__ __launch_bounds__(256, 2) void gemm_f(
    const float* __restrict__ X,
    const __half* __restrict__ Wf,
    const float* __restrict__ c1, const float* __restrict__ c2,
    float* __restrict__ out)
{
    extern __shared__ float smem[];
    float* sc1 = smem;
    float* sc2 = smem + 256;
    float* smu = smem + 512;
    float* srs = smem + 576;
    float* sAr = smem + HDR;                            // [2][64][RSTR] raw fp32
    uint32_t* sB = (uint32_t*)(smem + HDR + 2 * RAWB);  // [2 buf][256][BSTR] fp16
    float* sepi = smem + HDR;

    const int tid  = threadIdx.x;
    const int wid  = tid >> 5;
    const int lane = tid & 31;
    const int warp_m = (wid & 1) * 32;
    const int warp_n = (wid >> 1) * 64;
    const int R  = lane >> 2;
    const int cq = lane & 3;
    const int aq = tid & 7;

    int b_ = 0, j_ = 0, ts = 0, rows = 64, r0 = 0, m0 = 0;
    if (MODE == 0) {
        int bj = blockIdx.x >> 2, tile = blockIdx.x & 3;
        b_ = bj / JJ; j_ = bj % JJ;
        r0 = tile * 15;
        ts = (r0 * TT) / TR;
        int te = ((r0 + 15) * TT + TR - 1) / TR;
        rows = te - ts;
        sc1[tid] = c1[tid];
        sc2[tid] = c2[tid];
    } else {
        m0 = blockIdx.x * 64;
    }

    int offA0[2];
    #pragma unroll
    for (int it = 0; it < 2; ++it) {
        int row = (tid >> 3) + it * 32;
        if (MODE == 0) {
            int rc = min(row, rows - 1);
            offA0[it] = ((b_ * TT + ts + rc) * JJ + j_) * DD + aq * 4;
        } else {
            int yrow = m0 + row;
            int b = yrow / KSJ;
            int rem = yrow % KSJ;
            int s = rem / JJ, j = rem % JJ;
            offA0[it] = ((b * TR + g_topidx[b * KSEL + s]) * JJ + j) * DD + aq * 4;
        }
    }
    const float* Asrc = (MODE == 0) ? X : &g_xd[0];
    const bool stats_on = (wid < 2);
    float sAc[4] = {0,0,0,0}, ssAc[4] = {0,0,0,0};

    float acc[2][8][4];
    #pragma unroll
    for (int i = 0; i < 2; i++)
        #pragma unroll
        for (int j = 0; j < 8; j++)
            #pragma unroll
            for (int q = 0; q < 4; q++) acc[i][j][q] = 0.0f;

    const uint32_t bBase = smem_u32(sB) +
        4 * ((warp_n + (lane & 7) + ((lane >> 4) & 1) * 8) * BSTR + ((lane >> 3) & 1) * 4);

    auto stageA = [&](int kt, int buf) {
        #pragma unroll
        for (int it = 0; it < 2; ++it) {
            int row = (tid >> 3) + it * 32;
            uint32_t d = smem_u32(sAr + buf * RAWB + row * RSTR + aq * 4);
            CP_ASYNC(d, Asrc + offA0[it] + kt);
        }
    };
    auto stageB = [&](int kt, int buf) {
        #pragma unroll
        for (int it = 0; it < 4; ++it) {
            int f = tid + it * 256;
            int n = f >> 2;
            int q = f & 3;
            uint32_t dh = smem_u32(sB + buf * BB_ + n * BSTR + q * 4);
            CP_ASYNC(dh, Wf + (size_t)n * DD + kt + q * 8);
        }
    };

    // ---- prologue ----
    stageA(0, 0); stageB(0, 0);
    CP_COMMIT();
    CP_WAIT(0);
    __syncthreads();

    // ---- main loop: one barrier per chunk ----
    #pragma unroll 1
    for (int c = 0; c < 8; ++c) {
        const int buf = c & 1;
        if (c < 7) { stageA((c + 1) * 32, buf ^ 1); stageB((c + 1) * 32, buf ^ 1); CP_COMMIT(); }

        #pragma unroll
        for (int ks = 0; ks < 2; ++ks) {
            uint32_t ah[2][4];
            #pragma unroll
            for (int mt = 0; mt < 2; ++mt) {
                #pragma unroll
                for (int pr = 0; pr < 2; ++pr) {
                    int row = warp_m + mt * 16 + pr * 8 + R;
                    const float* bp = sAr + buf * RAWB + row * RSTR + ks * 16 + 2 * cq;
                    float2 v0 = *(const float2*)bp;
                    float2 v1 = *(const float2*)(bp + 8);
                    if (stats_on) {
                        int sl = mt * 2 + pr;
                        sAc[sl]  += v0.x + v0.y + v1.x + v1.y;
                        ssAc[sl] += v0.x*v0.x + v0.y*v0.y + v1.x*v1.x + v1.y*v1.y;
                    }
                    __half2 h0 = __floats2half2_rn(v0.x, v0.y);
                    __half2 h1 = __floats2half2_rn(v1.x, v1.y);
                    ah[mt][pr]     = *(uint32_t*)&h0;
                    ah[mt][2 + pr] = *(uint32_t*)&h1;
                }
            }
            #pragma unroll
            for (int p = 0; p < 4; ++p) {
                uint32_t bf[4];
                LDSM4(bf, bBase + 4 * (buf * BB_ + p * 16 * BSTR + ks * 8));
                const int n0 = 2 * p, n1 = 2 * p + 1;
                mma_f16(acc[0][n0], ah[0], bf[0], bf[1]);
                mma_f16(acc[1][n0], ah[1], bf[0], bf[1]);
                mma_f16(acc[0][n1], ah[0], bf[2], bf[3]);
                mma_f16(acc[1][n1], ah[1], bf[2], bf[3]);
            }
        }
        if (c < 7) CP_WAIT(0);
        __syncthreads();
    }

    // ---- finalize row stats ----
    if (stats_on) {
        #pragma unroll
        for (int sl = 0; sl < 4; ++sl) {
            float s_ = sAc[sl], ss_ = ssAc[sl];
            #pragma unroll
            for (int o = 1; o <= 2; o <<= 1) {
                s_  += __shfl_xor_sync(0xffffffffu, s_,  o);
                ss_ += __shfl_xor_sync(0xffffffffu, ss_, o);
            }
            if (cq == 0) {
                int row = warp_m + (sl >> 1) * 16 + (sl & 1) * 8 + R;
                float mu = s_ * (1.0f / DD);
                float ms = ss_ * (1.0f / DD);
                if (MODE == 0) {
                    smu[row] = mu;
                    srs[row] = rsqrtf(ms - mu * mu + 1e-5f);
                } else {
                    g_musel[m0 + row] = mu;
                    g_qsel[m0 + row]  = ms;
                }
            }
        }
    }

    // ---- epilogue ----
    if (MODE == 0) {
        __syncthreads();
        #pragma unroll
        for (int mt = 0; mt < 2; ++mt) {
            int mrow = warp_m + mt * 16 + R;
            float muA = smu[mrow],     rsA = srs[mrow];
            float muB = smu[mrow + 8], rsB = srs[mrow + 8];
            #pragma unroll
            for (int nt = 0; nt < 8; ++nt) {
                int n = warp_n + nt * 8 + 2 * cq;
                float2 cc1 = *(float2*)(sc1 + n);
                float2 cc2 = *(float2*)(sc2 + n);
                *(float2*)(sepi + mrow * ESTR + n) = make_float2(
                    gelu_f(rsA * acc[mt][nt][0] + cc1.x - muA * rsA * cc2.x),
                    gelu_f(rsA * acc[mt][nt][1] + cc1.y - muA * rsA * cc2.y));
                *(float2*)(sepi + (mrow + 8) * ESTR + n) = make_float2(
                    gelu_f(rsB * acc[mt][nt][2] + cc1.x - muB * rsB * cc2.x),
                    gelu_f(rsB * acc[mt][nt][3] + cc1.y - muB * rsB * cc2.y));
            }
        }
        __syncthreads();
        const int col = tid;
        #pragma unroll
        for (int rl = 0; rl < 15; ++rl) {
            int rg = r0 + rl;
            int s = (rg * TT) / TR - ts;
            int e = ((rg + 1) * TT + TR - 1) / TR - ts;
            float a = 0.0f;
            for (int t = s; t < e; ++t) a += sepi[t * ESTR + col];
            out[((size_t)((b_ * TR + rg) * JJ + j_)) * DD + col] = a / (float)(e - s);
        }
    } else {
        #pragma unroll
        for (int mt = 0; mt < 2; ++mt) {
            int mrow = m0 + warp_m + mt * 16 + R;
            #pragma unroll
            for (int nt = 0; nt < 8; ++nt) {
                int n = warp_n + nt * 8 + 2 * cq;
                *(float2*)(out + (size_t)mrow * DD + n) =
                    make_float2(acc[mt][nt][0], acc[mt][nt][1]);
                *(float2*)(out + (size_t)(mrow + 8) * DD + n) =
                    make_float2(acc[mt][nt][2], acc[mt][nt][3]);
            }
        }
    }
}

// ---------------- pooled mean over J ----------------
__global__ __launch_bounds__(256) void pooled_mean_kernel() {
    int id = blockIdx.x;
    int c = threadIdx.x;
    float acc = 0.0f;
    #pragma unroll
    for (int j = 0; j < JJ; ++j)
        acc += g_xd[((size_t)(id * JJ + j)) * DD + c];
    g_pm[(size_t)id * DD + c] = acc * (1.0f / JJ);
}

// ---------------- scorer: blocked GEMM, 32 rows/block, 120 blocks ----------------
#define SCROWS 32
#define SMEM_SC ((DD*DH + SCROWS*DD) * 4)   // 163840 B
__global__ __launch_bounds__(256) void scorer_fast(
    const float* __restrict__ w1, const float* __restrict__ b1,
    const float* __restrict__ w2, const float* __restrict__ b2)
{
    extern __shared__ float sm[];
    float* sw1 = sm;                 // [256][128]
    float* spm = sm + DD * DH;       // [32][256]
    const int tid = threadIdx.x;
    const int row0 = blockIdx.x * SCROWS;

    #pragma unroll 8
    for (int i = tid * 4; i < DD * DH; i += 1024)
        *(float4*)(sw1 + i) = *(const float4*)(w1 + i);
    #pragma unroll
    for (int i = tid * 4; i < SCROWS * DD; i += 1024)
        *(float4*)(spm + i) = *(const float4*)(g_pm + (size_t)row0 * DD + i);
    __syncthreads();

    const int hq = tid & 31;    // h = 4*hq .. 4*hq+3
    const int rg = tid >> 5;    // rows rg*4 .. rg*4+3
    float4 acc[4];
    #pragma unroll
    for (int r = 0; r < 4; ++r) acc[r] = make_float4(0.f, 0.f, 0.f, 0.f);

    #pragma unroll 4
    for (int c = 0; c < DD; ++c) {
        float4 wv = *(float4*)(sw1 + c * DH + hq * 4);
        #pragma unroll
        for (int r = 0; r < 4; ++r) {
            float p = spm[(rg * 4 + r) * DD + c];
            acc[r].x = fmaf(p, wv.x, acc[r].x);
            acc[r].y = fmaf(p, wv.y, acc[r].y);
            acc[r].z = fmaf(p, wv.z, acc[r].z);
            acc[r].w = fmaf(p, wv.w, acc[r].w);
        }
    }

    float4 b1v = *(const float4*)(b1 + hq * 4);
    float4 w2v = *(const float4*)(w2 + hq * 4);
    float b2v = b2[0];
    #pragma unroll
    for (int r = 0; r < 4; ++r) {
        float s = gelu_f(acc[r].x + b1v.x) * w2v.x
                + gelu_f(acc[r].y + b1v.y) * w2v.y
                + gelu_f(acc[r].z + b1v.z) * w2v.z
                + gelu_f(acc[r].w + b1v.w) * w2v.w;
        #pragma unroll
        for (int o = 16; o > 0; o >>= 1)
            s += __shfl_xor_sync(0xffffffffu, s, o);
        if (hq == 0)
            g_score[row0 + rg * 4 + r] = 1.0f / (1.0f + expf(-(s + b2v)));
    }
}

// ---------------- top-k selection ----------------
__global__ __launch_bounds__(64) void topk_kernel() {
    __shared__ float sc[TR];
    __shared__ int sel[TR];
    int b = blockIdx.x, tid = threadIdx.x;
    if (tid < TR) sc[tid] = g_score[b * TR + tid];
    __syncthreads();
    if (tid < TR) {
        float s = sc[tid];
        int rank = 0;
        for (int q = 0; q < TR; ++q) {
            float sq = sc[q];
            rank += (sq > s) || (sq == s && q < tid);
        }
        sel[tid] = (rank < KSEL) ? 1 : 0;
    }
    __syncthreads();
    if (tid == 0) {
        int pos = 0;
        for (int r = 0; r < TR; ++r)
            if (sel[r]) g_topidx[b * KSEL + (pos++)] = r;
    }
}

// ---------------- cross-dot: E[xd_sel[p] * xd_sel[p+1]] ----------------
__global__ __launch_bounds__(256) void crossdot_kernel() {
    int id = blockIdx.x * 8 + (threadIdx.x >> 5);
    int lane = threadIdx.x & 31;
    if (id >= BB * (KSEL - 1) * JJ) return;
    int j = id % JJ;
    int p = (id / JJ) % (KSEL - 1);
    int b = id / (JJ * (KSEL - 1));
    int i0 = g_topidx[b * KSEL + p];
    int i1 = g_topidx[b * KSEL + p + 1];
    const float* r0 = g_xd + (size_t)((b * TR + i0) * JJ + j) * DD;
    const float* r1 = g_xd + (size_t)((b * TR + i1) * JJ + j) * DD;
    float s = 0.0f;
    #pragma unroll
    for (int h = 0; h < 2; ++h) {
        int c = h * 128 + lane * 4;
        float4 a = *(const float4*)(r0 + c);
        float4 d = *(const float4*)(r1 + c);
        s += a.x*d.x + a.y*d.y + a.z*d.z + a.w*d.w;
    }
    #pragma unroll
    for (int o = 16; o > 0; o >>= 1)
        s += __shfl_xor_sync(0xffffffffu, s, o);
    if (lane == 0) g_q01[id] = s * (1.0f / DD);
}

// ---------------- final epilogue: lerp(Y) affine + gelu + residual ----------------
__global__ __launch_bounds__(256) void epilogue_e(const float* __restrict__ X,
                                                  float* __restrict__ out) {
    int m = blockIdx.x * 8 + (threadIdx.x >> 5);
    int lane = threadIdx.x & 31;
    int b = m / TJ, rem = m % TJ;
    int t = rem / JJ, j = rem % JJ;

    float src = (t + 0.5f) * (float)(30.0 / 243.0) - 0.5f;
    src = fminf(fmaxf(src, 0.0f), (float)(KSEL - 1));
    int x0 = (int)src;
    int x1 = min(x0 + 1, KSEL - 1);
    float w = src - (float)x0;

    int ys0 = (b * KSEL + x0) * JJ + j;
    int ys1 = (b * KSEL + x1) * JJ + j;
    float mu0 = g_musel[ys0], q0 = g_qsel[ys0];
    float mu1 = g_musel[ys1], q1 = g_qsel[ys1];
    float q01 = (x1 > x0) ? g_q01[(b * (KSEL - 1) + x0) * JJ + j] : q0;
    float iw = 1.0f - w;
    float mu = iw * mu0 + w * mu1;
    float es = iw * iw * q0 + 2.0f * w * iw * q01 + w * w * q1;
    float rs = rsqrtf(es - mu * mu + 1e-5f);
    float mrs = mu * rs;

    const float* y0 = g_Y + (size_t)ys0 * DD;
    const float* y1 = g_Y + (size_t)ys1 * DD;
    #pragma unroll
    for (int h = 0; h < 2; ++h) {
        int c = h * 128 + lane * 4;
        float4 a = *(const float4*)(y0 + c);
        float4 d = *(const float4*)(y1 + c);
        float4 cc1 = *(const float4*)(g_c1op + c);
        float4 cc2 = *(const float4*)(g_c2op + c);
        float4 xr = *(const float4*)(X + (size_t)m * DD + c);
        float4 o;
        o.x = gelu_f(rs * (a.x + (d.x - a.x) * w) + cc1.x - mrs * cc2.x) + xr.x;
        o.y = gelu_f(rs * (a.y + (d.y - a.y) * w) + cc1.y - mrs * cc2.y) + xr.y;
        o.z = gelu_f(rs * (a.z + (d.z - a.z) * w) + cc1.z - mrs * cc2.z) + xr.z;
        o.w = gelu_f(rs * (a.w + (d.w - a.w) * w) + cc1.w - mrs * cc2.w) + xr.w;
        *(float4*)(out + (size_t)m * DD + c) = o;
    }
}

// ---------------- launch ----------------
extern "C" void kernel_launch(void* const* d_in, const int* in_sizes, int n_in,
                              void* d_out, int out_size) {
    const float* x       = (const float*)d_in[0];
    const float* fp_g    = (const float*)d_in[1];
    const float* fp_b    = (const float*)d_in[2];
    const float* fp_w    = (const float*)d_in[3];
    const float* fp_bias = (const float*)d_in[4];
    const float* sc_w1   = (const float*)d_in[5];
    const float* sc_b1   = (const float*)d_in[6];
    const float* sc_w2   = (const float*)d_in[7];
    const float* sc_b2   = (const float*)d_in[8];
    const float* op_g    = (const float*)d_in[9];
    const float* op_b    = (const float*)d_in[10];
    const float* op_w    = (const float*)d_in[11];
    const float* op_bias = (const float*)d_in[12];
    float* out = (float*)d_out;

    float *xd_ptr, *y_ptr, *c1fp, *c2fp, *c1op, *c2op;
    __half *w0f, *w1f;
    cudaGetSymbolAddress((void**)&xd_ptr, g_xd);
    cudaGetSymbolAddress((void**)&y_ptr, g_Y);
    cudaGetSymbolAddress((void**)&c1fp, g_c1fp);
    cudaGetSymbolAddress((void**)&c2fp, g_c2fp);
    cudaGetSymbolAddress((void**)&c1op, g_c1op);
    cudaGetSymbolAddress((void**)&c2op, g_c2op);
    cudaGetSymbolAddress((void**)&w0f, g_w0f);
    cudaGetSymbolAddress((void**)&w1f, g_w1f);

    cudaFuncSetAttribute(gemm_f<0>, cudaFuncAttributeMaxDynamicSharedMemorySize, SMEM_G);
    cudaFuncSetAttribute(gemm_f<1>, cudaFuncAttributeMaxDynamicSharedMemorySize, SMEM_G);
    cudaFuncSetAttribute(scorer_fast, cudaFuncAttributeMaxDynamicSharedMemorySize, SMEM_SC);

    prep_w2<<<512, 256>>>(fp_w, fp_g, op_w, op_g, w0f, w1f);
    calc_c2<<<512, 256>>>(fp_w, fp_b, fp_g, fp_bias, op_w, op_b, op_g, op_bias,
                          c1fp, c2fp, c1op, c2op);
    gemm_f<0><<<BB * JJ * 4, 256, SMEM_G>>>(x, w0f, c1fp, c2fp, xd_ptr);
    pooled_mean_kernel<<<BB * TR, 256>>>();
    scorer_fast<<<BB * TR / SCROWS, 256, SMEM_SC>>>(sc_w1, sc_b1, sc_w2, sc_b2);
    topk_kernel<<<BB, 64>>>();
    gemm_f<1><<<YROWS / 64, 256, SMEM_G>>>(x, w1f, c1op, c2op, y_ptr);
    crossdot_kernel<<<(BB * (KSEL - 1) * JJ + 7) / 8, 256>>>();
    epilogue_e<<<MROWS / 8, 256>>>(x, out);
}

// round 16
// speedup vs baseline: 1.1751x; 1.0170x over previous
#include <cuda_runtime.h>
#include <cuda_fp16.h>
#include <math.h>
#include <stdint.h>

// ---------------- problem constants ----------------
#define BB 64
#define TT 243
#define JJ 17
#define DD 256
#define DH 128
#define TR 60
#define KSEL 30
#define KSJ (KSEL*JJ)          // 510
#define YROWS (BB*KSJ)         // 32640
#define MROWS (BB*TT*JJ)       // 264384
#define TJ (TT*JJ)             // 4131

// ---------------- scratch ----------------
__device__ float g_xd[(size_t)BB*TR*JJ*DD];
__device__ float g_score[BB*TR];
__device__ int   g_topidx[BB*KSEL];
__device__ float g_Y[(size_t)YROWS*DD];
__device__ float g_musel[YROWS], g_qsel[YROWS];
__device__ float g_q01[BB*(KSEL-1)*JJ];
__device__ float g_c1fp[DD], g_c2fp[DD];
__device__ float g_c1op[DD], g_c2op[DD];
__device__ __half g_w0f[DD*DD];     // (fp_g ⊙ fp_w)^T fp16
__device__ __half g_w1f[DD*DD];     // (op_g ⊙ op_w)^T fp16

__device__ __forceinline__ float gelu_f(float x) {
    return 0.5f * x * (1.0f + erff(x * 0.70710678118654752f));
}
__device__ __forceinline__ uint32_t smem_u32(const void* p) {
    uint32_t a;
    asm("{ .reg .u64 t; cvta.to.shared.u64 t, %1; cvt.u32.u64 %0, t; }" : "=r"(a) : "l"(p));
    return a;
}
__device__ __forceinline__ void mma_f16(float* d, const uint32_t* a,
                                        uint32_t b0, uint32_t b1) {
    asm volatile(
        "mma.sync.aligned.m16n8k16.row.col.f32.f16.f16.f32 "
        "{%0,%1,%2,%3}, {%4,%5,%6,%7}, {%8,%9}, {%0,%1,%2,%3};"
        : "+f"(d[0]), "+f"(d[1]), "+f"(d[2]), "+f"(d[3])
        : "r"(a[0]), "r"(a[1]), "r"(a[2]), "r"(a[3]), "r"(b0), "r"(b1));
}
#define LDSM4(r, addr) \
    asm volatile("ldmatrix.sync.aligned.m8n8.x4.shared.b16 {%0,%1,%2,%3}, [%4];" \
        : "=r"((r)[0]), "=r"((r)[1]), "=r"((r)[2]), "=r"((r)[3]) : "r"(addr))
#define CP_ASYNC(dst, src) asm volatile("cp.async.cg.shared.global [%0], [%1], 16;" :: "r"(dst), "l"(src))
#define CP_COMMIT()        asm volatile("cp.async.commit_group;" ::: "memory")
#define CP_WAIT(n)         asm volatile("cp.async.wait_group %0;" :: "n"(n) : "memory")

// smem geometry (3-stage pipeline)
#define RSTR 40
#define RAWB (64*RSTR)          // 2560 floats per raw A buffer
#define BSTR 20
#define BB_  (256*BSTR)         // 5120 u32 per B buffer (fp16)
#define HDR 832
#define SMEM_G ((HDR + 3*RAWB + 3*BB_) * 4)   // 95488 B (compute 23040 >= epi 16512)
#define ESTR 258

// ---------------- prep (merged): W' transpose+fp16 AND c1/c2 vectors ----------------
__global__ __launch_bounds__(256) void prep_all(
    const float* __restrict__ W0, const float* __restrict__ g0,
    const float* __restrict__ be0, const float* __restrict__ bi0,
    const float* __restrict__ W1, const float* __restrict__ g1,
    const float* __restrict__ be1, const float* __restrict__ bi1,
    __half* __restrict__ W0f, __half* __restrict__ W1f,
    float* __restrict__ c1a, float* __restrict__ c2a,
    float* __restrict__ c1b, float* __restrict__ c2b)
{
    __shared__ float r1[256], r2[256];
    int which = blockIdx.x >> 8;
    int n = blockIdx.x & 255, k = threadIdx.x;
    const float* W = which ? W1 : W0;
    const float* g = which ? g1 : g0;
    // column n of W (stride-DD reads), used for both outputs
    float w = W[k * DD + n];
    // transpose + scale + fp16: element (k,n) -> Wf[n*DD + k]
    (which ? W1f : W0f)[n * DD + k] = __float2half_rn(w * g[k]);
    r1[k] = (which ? be1 : be0)[k] * w;
    r2[k] = g[k] * w;
    __syncthreads();
    #pragma unroll
    for (int s = 128; s > 0; s >>= 1) {
        if (k < s) { r1[k] += r1[k + s]; r2[k] += r2[k + s]; }
        __syncthreads();
    }
    if (k == 0) {
        (which ? c1b : c1a)[n] = r1[0] + (which ? bi1 : bi0)[n];
        (which ? c2b : c2a)[n] = r2[0];
    }
}

// ---------------- fp16 x1 mma GEMM, 3-stage cp.async pipeline ----------------
// MODE 0: A = raw x t-slab of (b,j); epilogue gelu(affine) + pool -> g_xd
// MODE 1: A = selected xd rows; plain Y store + row stats
template <int MODE>
__global__ __launch_bounds__(256, 2) void gemm_f(
    const float* __restrict__ X,
    const __half* __restrict__ Wf,
    const float* __restrict__ c1, const float* __restrict__ c2,
    float* __restrict__ out)
{
    extern __shared__ float smem[];
    float* sc1 = smem;
    float* sc2 = smem + 256;
    float* smu = smem + 512;
    float* srs = smem + 576;
    float* sAr = smem + HDR;                            // [3][64][RSTR] raw fp32
    uint32_t* sB = (uint32_t*)(smem + HDR + 3 * RAWB);  // [3][256][BSTR] fp16
    float* sepi = smem + HDR;

    const int tid  = threadIdx.x;
    const int wid  = tid >> 5;
    const int lane = tid & 31;
    const int warp_m = (wid & 1) * 32;
    const int warp_n = (wid >> 1) * 64;
    const int R  = lane >> 2;
    const int cq = lane & 3;
    const int aq = tid & 7;

    int b_ = 0, j_ = 0, ts = 0, rows = 64, r0 = 0, m0 = 0;
    if (MODE == 0) {
        int bj = blockIdx.x >> 2, tile = blockIdx.x & 3;
        b_ = bj / JJ; j_ = bj % JJ;
        r0 = tile * 15;
        ts = (r0 * TT) / TR;
        int te = ((r0 + 15) * TT + TR - 1) / TR;
        rows = te - ts;
        sc1[tid] = c1[tid];
        sc2[tid] = c2[tid];
    } else {
        m0 = blockIdx.x * 64;
    }

    int offA0[2];
    #pragma unroll
    for (int it = 0; it < 2; ++it) {
        int row = (tid >> 3) + it * 32;
        if (MODE == 0) {
            int rc = min(row, rows - 1);
            offA0[it] = ((b_ * TT + ts + rc) * JJ + j_) * DD + aq * 4;
        } else {
            int yrow = m0 + row;
            int b = yrow / KSJ;
            int rem = yrow % KSJ;
            int s = rem / JJ, j = rem % JJ;
            offA0[it] = ((b * TR + g_topidx[b * KSEL + s]) * JJ + j) * DD + aq * 4;
        }
    }
    const float* Asrc = (MODE == 0) ? X : &g_xd[0];
    const bool stats_on = (wid < 2);
    float sAc[4] = {0,0,0,0}, ssAc[4] = {0,0,0,0};

    float acc[2][8][4];
    #pragma unroll
    for (int i = 0; i < 2; i++)
        #pragma unroll
        for (int j = 0; j < 8; j++)
            #pragma unroll
            for (int q = 0; q < 4; q++) acc[i][j][q] = 0.0f;

    const uint32_t bBase = smem_u32(sB) +
        4 * ((warp_n + (lane & 7) + ((lane >> 4) & 1) * 8) * BSTR + ((lane >> 3) & 1) * 4);

    auto stageA = [&](int kt, int buf) {
        #pragma unroll
        for (int it = 0; it < 2; ++it) {
            int row = (tid >> 3) + it * 32;
            uint32_t d = smem_u32(sAr + buf * RAWB + row * RSTR + aq * 4);
            CP_ASYNC(d, Asrc + offA0[it] + kt);
        }
    };
    auto stageB = [&](int kt, int buf) {
        #pragma unroll
        for (int it = 0; it < 4; ++it) {
            int f = tid + it * 256;
            int n = f >> 2;
            int q = f & 3;
            uint32_t dh = smem_u32(sB + buf * BB_ + n * BSTR + q * 4);
            CP_ASYNC(dh, Wf + (size_t)n * DD + kt + q * 8);
        }
    };

    // ---- prologue: 2 chunks in flight ----
    stageA(0, 0); stageB(0, 0); CP_COMMIT();
    stageA(32, 1); stageB(32, 1); CP_COMMIT();

    // ---- main loop: 1 barrier/chunk, 2-chunk-deep pipeline ----
    #pragma unroll 1
    for (int c = 0; c < 8; ++c) {
        const int buf = c % 3;
        if (c < 7) CP_WAIT(1); else CP_WAIT(0);   // chunk c complete
        __syncthreads();                          // publish chunk c; free buf (c+2)%3
        if (c + 2 < 8) {
            stageA((c + 2) * 32, (c + 2) % 3);
            stageB((c + 2) * 32, (c + 2) % 3);
            CP_COMMIT();
        }

        #pragma unroll
        for (int ks = 0; ks < 2; ++ks) {
            uint32_t ah[2][4];
            #pragma unroll
            for (int mt = 0; mt < 2; ++mt) {
                #pragma unroll
                for (int pr = 0; pr < 2; ++pr) {
                    int row = warp_m + mt * 16 + pr * 8 + R;
                    const float* bp = sAr + buf * RAWB + row * RSTR + ks * 16 + 2 * cq;
                    float2 v0 = *(const float2*)bp;
                    float2 v1 = *(const float2*)(bp + 8);
                    if (stats_on) {
                        int sl = mt * 2 + pr;
                        sAc[sl]  += v0.x + v0.y + v1.x + v1.y;
                        ssAc[sl] += v0.x*v0.x + v0.y*v0.y + v1.x*v1.x + v1.y*v1.y;
                    }
                    __half2 h0 = __floats2half2_rn(v0.x, v0.y);
                    __half2 h1 = __floats2half2_rn(v1.x, v1.y);
                    ah[mt][pr]     = *(uint32_t*)&h0;
                    ah[mt][2 + pr] = *(uint32_t*)&h1;
                }
            }
            #pragma unroll
            for (int p = 0; p < 4; ++p) {
                uint32_t bf[4];
                LDSM4(bf, bBase + 4 * (buf * BB_ + p * 16 * BSTR + ks * 8));
                const int n0 = 2 * p, n1 = 2 * p + 1;
                mma_f16(acc[0][n0], ah[0], bf[0], bf[1]);
                mma_f16(acc[1][n0], ah[1], bf[0], bf[1]);
                mma_f16(acc[0][n1], ah[0], bf[2], bf[3]);
                mma_f16(acc[1][n1], ah[1], bf[2], bf[3]);
            }
        }
    }
    __syncthreads();

    // ---- finalize row stats (warps 0,1 own rows 0-63) ----
    if (stats_on) {
        #pragma unroll
        for (int sl = 0; sl < 4; ++sl) {
            float s_ = sAc[sl], ss_ = ssAc[sl];
            #pragma unroll
            for (int o = 1; o <= 2; o <<= 1) {
                s_  += __shfl_xor_sync(0xffffffffu, s_,  o);
                ss_ += __shfl_xor_sync(0xffffffffu, ss_, o);
            }
            if (cq == 0) {
                int row = warp_m + (sl >> 1) * 16 + (sl & 1) * 8 + R;
                float mu = s_ * (1.0f / DD);
                float ms = ss_ * (1.0f / DD);
                if (MODE == 0) {
                    smu[row] = mu;
                    srs[row] = rsqrtf(ms - mu * mu + 1e-5f);
                } else {
                    g_musel[m0 + row] = mu;
                    g_qsel[m0 + row]  = ms;
                }
            }
        }
    }

    // ---- epilogue ----
    if (MODE == 0) {
        __syncthreads();
        #pragma unroll
        for (int mt = 0; mt < 2; ++mt) {
            int mrow = warp_m + mt * 16 + R;
            float muA = smu[mrow],     rsA = srs[mrow];
            float muB = smu[mrow + 8], rsB = srs[mrow + 8];
            #pragma unroll
            for (int nt = 0; nt < 8; ++nt) {
                int n = warp_n + nt * 8 + 2 * cq;
                float2 cc1 = *(float2*)(sc1 + n);
                float2 cc2 = *(float2*)(sc2 + n);
                *(float2*)(sepi + mrow * ESTR + n) = make_float2(
                    gelu_f(rsA * acc[mt][nt][0] + cc1.x - muA * rsA * cc2.x),
                    gelu_f(rsA * acc[mt][nt][1] + cc1.y - muA * rsA * cc2.y));
                *(float2*)(sepi + (mrow + 8) * ESTR + n) = make_float2(
                    gelu_f(rsB * acc[mt][nt][2] + cc1.x - muB * rsB * cc2.x),
                    gelu_f(rsB * acc[mt][nt][3] + cc1.y - muB * rsB * cc2.y));
            }
        }
        __syncthreads();
        const int col = tid;
        #pragma unroll
        for (int rl = 0; rl < 15; ++rl) {
            int rg = r0 + rl;
            int s = (rg * TT) / TR - ts;
            int e = ((rg + 1) * TT + TR - 1) / TR - ts;
            float a = 0.0f;
            for (int t = s; t < e; ++t) a += sepi[t * ESTR + col];
            out[((size_t)((b_ * TR + rg) * JJ + j_)) * DD + col] = a / (float)(e - s);
        }
    } else {
        #pragma unroll
        for (int mt = 0; mt < 2; ++mt) {
            int mrow = m0 + warp_m + mt * 16 + R;
            #pragma unroll
            for (int nt = 0; nt < 8; ++nt) {
                int n = warp_n + nt * 8 + 2 * cq;
                *(float2*)(out + (size_t)mrow * DD + n) =
                    make_float2(acc[mt][nt][0], acc[mt][nt][1]);
                *(float2*)(out + (size_t)(mrow + 8) * DD + n) =
                    make_float2(acc[mt][nt][2], acc[mt][nt][3]);
            }
        }
    }
}

// ---------------- scorer (fused J-mean): blocked GEMM, 32 pm-rows/block ----------------
#define SCROWS 32
#define SMEM_SC ((DD*DH + SCROWS*DD) * 4)   // 163840 B
__global__ __launch_bounds__(256) void scorer_fast(
    const float* __restrict__ w1, const float* __restrict__ b1,
    const float* __restrict__ w2, const float* __restrict__ b2)
{
    extern __shared__ float sm[];
    float* sw1 = sm;                 // [256][128]
    float* spm = sm + DD * DH;       // [32][256]
    const int tid = threadIdx.x;
    const int row0 = blockIdx.x * SCROWS;   // pm-row = b*TR + r

    #pragma unroll 8
    for (int i = tid * 4; i < DD * DH; i += 1024)
        *(float4*)(sw1 + i) = *(const float4*)(w1 + i);
    // fused pooled-mean over J: spm[rr][c] = mean_j g_xd[(row0+rr)*JJ+j][c]
    #pragma unroll
    for (int i = tid * 4; i < SCROWS * DD; i += 1024) {
        int rr = i >> 8;            // local pm-row
        int cc = i & 255;
        const float* base = g_xd + ((size_t)(row0 + rr) * JJ) * DD + cc;
        float4 s4 = make_float4(0.f, 0.f, 0.f, 0.f);
        #pragma unroll
        for (int j = 0; j < JJ; ++j) {
            float4 v = *(const float4*)(base + j * DD);
            s4.x += v.x; s4.y += v.y; s4.z += v.z; s4.w += v.w;
        }
        const float inv = 1.0f / JJ;
        *(float4*)(spm + i) = make_float4(s4.x * inv, s4.y * inv, s4.z * inv, s4.w * inv);
    }
    __syncthreads();

    const int hq = tid & 31;    // h = 4*hq .. 4*hq+3
    const int rg = tid >> 5;    // rows rg*4 .. rg*4+3
    float4 acc[4];
    #pragma unroll
    for (int r = 0; r < 4; ++r) acc[r] = make_float4(0.f, 0.f, 0.f, 0.f);

    #pragma unroll 4
    for (int c = 0; c < DD; ++c) {
        float4 wv = *(float4*)(sw1 + c * DH + hq * 4);
        #pragma unroll
        for (int r = 0; r < 4; ++r) {
            float p = spm[(rg * 4 + r) * DD + c];
            acc[r].x = fmaf(p, wv.x, acc[r].x);
            acc[r].y = fmaf(p, wv.y, acc[r].y);
            acc[r].z = fmaf(p, wv.z, acc[r].z);
            acc[r].w = fmaf(p, wv.w, acc[r].w);
        }
    }

    float4 b1v = *(const float4*)(b1 + hq * 4);
    float4 w2v = *(const float4*)(w2 + hq * 4);
    float b2v = b2[0];
    #pragma unroll
    for (int r = 0; r < 4; ++r) {
        float s = gelu_f(acc[r].x + b1v.x) * w2v.x
                + gelu_f(acc[r].y + b1v.y) * w2v.y
                + gelu_f(acc[r].z + b1v.z) * w2v.z
                + gelu_f(acc[r].w + b1v.w) * w2v.w;
        #pragma unroll
        for (int o = 16; o > 0; o >>= 1)
            s += __shfl_xor_sync(0xffffffffu, s, o);
        if (hq == 0)
            g_score[row0 + rg * 4 + r] = 1.0f / (1.0f + expf(-(s + b2v)));
    }
}

// ---------------- top-k selection ----------------
__global__ __launch_bounds__(64) void topk_kernel() {
    __shared__ float sc[TR];
    __shared__ int sel[TR];
    int b = blockIdx.x, tid = threadIdx.x;
    if (tid < TR) sc[tid] = g_score[b * TR + tid];
    __syncthreads();
    if (tid < TR) {
        float s = sc[tid];
        int rank = 0;
        for (int q = 0; q < TR; ++q) {
            float sq = sc[q];
            rank += (sq > s) || (sq == s && q < tid);
        }
        sel[tid] = (rank < KSEL) ? 1 : 0;
    }
    __syncthreads();
    if (tid == 0) {
        int pos = 0;
        for (int r = 0; r < TR; ++r)
            if (sel[r]) g_topidx[b * KSEL + (pos++)] = r;
    }
}

// ---------------- cross-dot: E[xd_sel[p] * xd_sel[p+1]] ----------------
__global__ __launch_bounds__(256) void crossdot_kernel() {
    int id = blockIdx.x * 8 + (threadIdx.x >> 5);
    int lane = threadIdx.x & 31;
    if (id >= BB * (KSEL - 1) * JJ) return;
    int j = id % JJ;
    int p = (id / JJ) % (KSEL - 1);
    int b = id / (JJ * (KSEL - 1));
    int i0 = g_topidx[b * KSEL + p];
    int i1 = g_topidx[b * KSEL + p + 1];
    const float* r0 = g_xd + (size_t)((b * TR + i0) * JJ + j) * DD;
    const float* r1 = g_xd + (size_t)((b * TR + i1) * JJ + j) * DD;
    float s = 0.0f;
    #pragma unroll
    for (int h = 0; h < 2; ++h) {
        int c = h * 128 + lane * 4;
        float4 a = *(const float4*)(r0 + c);
        float4 d = *(const float4*)(r1 + c);
        s += a.x*d.x + a.y*d.y + a.z*d.z + a.w*d.w;
    }
    #pragma unroll
    for (int o = 16; o > 0; o >>= 1)
        s += __shfl_xor_sync(0xffffffffu, s, o);
    if (lane == 0) g_q01[id] = s * (1.0f / DD);
}

// ---------------- final epilogue: lerp(Y) affine + gelu + residual ----------------
__global__ __launch_bounds__(256) void epilogue_e(const float* __restrict__ X,
                                                  float* __restrict__ out) {
    int m = blockIdx.x * 8 + (threadIdx.x >> 5);
    int lane = threadIdx.x & 31;
    int b = m / TJ, rem = m % TJ;
    int t = rem / JJ, j = rem % JJ;

    float src = (t + 0.5f) * (float)(30.0 / 243.0) - 0.5f;
    src = fminf(fmaxf(src, 0.0f), (float)(KSEL - 1));
    int x0 = (int)src;
    int x1 = min(x0 + 1, KSEL - 1);
    float w = src - (float)x0;

    int ys0 = (b * KSEL + x0) * JJ + j;
    int ys1 = (b * KSEL + x1) * JJ + j;
    float mu0 = g_musel[ys0], q0 = g_qsel[ys0];
    float mu1 = g_musel[ys1], q1 = g_qsel[ys1];
    float q01 = (x1 > x0) ? g_q01[(b * (KSEL - 1) + x0) * JJ + j] : q0;
    float iw = 1.0f - w;
    float mu = iw * mu0 + w * mu1;
    float es = iw * iw * q0 + 2.0f * w * iw * q01 + w * w * q1;
    float rs = rsqrtf(es - mu * mu + 1e-5f);
    float mrs = mu * rs;

    const float* y0 = g_Y + (size_t)ys0 * DD;
    const float* y1 = g_Y + (size_t)ys1 * DD;
    #pragma unroll
    for (int h = 0; h < 2; ++h) {
        int c = h * 128 + lane * 4;
        float4 a = *(const float4*)(y0 + c);
        float4 d = *(const float4*)(y1 + c);
        float4 cc1 = *(const float4*)(g_c1op + c);
        float4 cc2 = *(const float4*)(g_c2op + c);
        float4 xr = *(const float4*)(X + (size_t)m * DD + c);
        float4 o;
        o.x = gelu_f(rs * (a.x + (d.x - a.x) * w) + cc1.x - mrs * cc2.x) + xr.x;
        o.y = gelu_f(rs * (a.y + (d.y - a.y) * w) + cc1.y - mrs * cc2.y) + xr.y;
        o.z = gelu_f(rs * (a.z + (d.z - a.z) * w) + cc1.z - mrs * cc2.z) + xr.z;
        o.w = gelu_f(rs * (a.w + (d.w - a.w) * w) + cc1.w - mrs * cc2.w) + xr.w;
        *(float4*)(out + (size_t)m * DD + c) = o;
    }
}

// ---------------- launch ----------------
extern "C" void kernel_launch(void* const* d_in, const int* in_sizes, int n_in,
                              void* d_out, int out_size) {
    const float* x       = (const float*)d_in[0];
    const float* fp_g    = (const float*)d_in[1];
    const float* fp_b    = (const float*)d_in[2];
    const float* fp_w    = (const float*)d_in[3];
    const float* fp_bias = (const float*)d_in[4];
    const float* sc_w1   = (const float*)d_in[5];
    const float* sc_b1   = (const float*)d_in[6];
    const float* sc_w2   = (const float*)d_in[7];
    const float* sc_b2   = (const float*)d_in[8];
    const float* op_g    = (const float*)d_in[9];
    const float* op_b    = (const float*)d_in[10];
    const float* op_w    = (const float*)d_in[11];
    const float* op_bias = (const float*)d_in[12];
    float* out = (float*)d_out;

    float *xd_ptr, *y_ptr, *c1fp, *c2fp, *c1op, *c2op;
    __half *w0f, *w1f;
    cudaGetSymbolAddress((void**)&xd_ptr, g_xd);
    cudaGetSymbolAddress((void**)&y_ptr, g_Y);
    cudaGetSymbolAddress((void**)&c1fp, g_c1fp);
    cudaGetSymbolAddress((void**)&c2fp, g_c2fp);
    cudaGetSymbolAddress((void**)&c1op, g_c1op);
    cudaGetSymbolAddress((void**)&c2op, g_c2op);
    cudaGetSymbolAddress((void**)&w0f, g_w0f);
    cudaGetSymbolAddress((void**)&w1f, g_w1f);

    cudaFuncSetAttribute(gemm_f<0>, cudaFuncAttributeMaxDynamicSharedMemorySize, SMEM_G);
    cudaFuncSetAttribute(gemm_f<1>, cudaFuncAttributeMaxDynamicSharedMemorySize, SMEM_G);
    cudaFuncSetAttribute(scorer_fast, cudaFuncAttributeMaxDynamicSharedMemorySize, SMEM_SC);

    prep_all<<<512, 256>>>(fp_w, fp_g, fp_b, fp_bias, op_w, op_g, op_b, op_bias,
                           w0f, w1f, c1fp, c2fp, c1op, c2op);
    gemm_f<0><<<BB * JJ * 4, 256, SMEM_G>>>(x, w0f, c1fp, c2fp, xd_ptr);
    scorer_fast<<<BB * TR / SCROWS, 256, SMEM_SC>>>(sc_w1, sc_b1, sc_w2, sc_b2);
    topk_kernel<<<BB, 64>>>();
    gemm_f<1><<<YROWS / 64, 256, SMEM_G>>>(x, w1f, c1op, c2op, y_ptr);
    crossdot_kernel<<<(BB * (KSEL - 1) * JJ + 7) / 8, 256>>>();
    epilogue_e<<<MROWS / 8, 256>>>(x, out);
}